// round 5
// baseline (speedup 1.0000x reference)
#include <cuda_runtime.h>

#define BATCH 32
#define CH    512
#define NGRP  16
#define CPG   32           // channels per group
#define NTOK  1024         // 32*32 spatial
#define GSIZE (CPG * NTOK) // elements per (batch, group)

// ---------------- scratch (static device globals; runtime alloc is forbidden) ----
__device__ float g_hn[(size_t)BATCH * CH * NTOK];     // groupnorm output
__device__ float g_q [(size_t)BATCH * CH * NTOK];
__device__ float g_k [(size_t)BATCH * CH * NTOK];
__device__ float g_v [(size_t)BATCH * CH * NTOK];
__device__ float g_s [(size_t)BATCH * NTOK * NTOK];   // scores / attn (in place)
__device__ float g_o [(size_t)BATCH * CH * NTOK];     // attn output pre-proj

// ---------------- GroupNorm -------------------------------------------------------
__global__ __launch_bounds__(256) void groupnorm_kernel(
    const float* __restrict__ x, const float* __restrict__ gamma,
    const float* __restrict__ beta, float* __restrict__ hn)
{
    int b = blockIdx.x / NGRP;
    int g = blockIdx.x % NGRP;
    const float* xp = x  + ((size_t)b * CH + g * CPG) * NTOK;
    float*       hp = hn + ((size_t)b * CH + g * CPG) * NTOK;
    int tid = threadIdx.x;

    float s = 0.f, s2 = 0.f;
    for (int i = tid; i < GSIZE; i += 256) {
        float v = xp[i];
        s += v; s2 += v * v;
    }
    __shared__ float rs[256], rs2[256];
    rs[tid] = s; rs2[tid] = s2;
    __syncthreads();
    for (int o = 128; o > 0; o >>= 1) {
        if (tid < o) { rs[tid] += rs[tid + o]; rs2[tid] += rs2[tid + o]; }
        __syncthreads();
    }
    float mean = rs[0] * (1.0f / GSIZE);
    float var  = rs2[0] * (1.0f / GSIZE) - mean * mean;
    float rstd = rsqrtf(var + 1e-6f);

    for (int i = tid; i < GSIZE; i += 256) {
        int c = g * CPG + i / NTOK;
        hp[i] = (xp[i] - mean) * rstd * gamma[c] + beta[c];
    }
}

// ---------------- shared GEMM inner product (64x64 tile, 4x4/thread) -------------
__device__ __forceinline__ void mma_tile(const float (*As)[68], const float (*Bs)[68],
                                         float acc[4][4], int tx, int ty)
{
#pragma unroll
    for (int kk = 0; kk < 16; kk++) {
        float4 a = *(const float4*)&As[kk][ty * 4];
        float4 b = *(const float4*)&Bs[kk][tx * 4];
        float ai[4] = {a.x, a.y, a.z, a.w};
        float bj[4] = {b.x, b.y, b.z, b.w};
#pragma unroll
        for (int i = 0; i < 4; i++)
#pragma unroll
            for (int j = 0; j < 4; j++)
                acc[i][j] += ai[i] * bj[j];
    }
}

// ---------------- NN GEMM: C[b] = A(M=512,K=512) * B[b](K=512,N=1024) + bias (+resid)
__global__ __launch_bounds__(256) void gemm_nn(
    const float* __restrict__ A, const float* __restrict__ B,
    const float* __restrict__ bias, const float* __restrict__ resid,
    float* __restrict__ C)
{
    const int Kk = CH, Nn = NTOK;
    int bz = blockIdx.z;
    int m0 = blockIdx.y * 64, n0 = blockIdx.x * 64;
    const float* Bb = B + (size_t)bz * Kk * Nn;

    __shared__ float As[16][68];
    __shared__ float Bs[16][68];
    int tid = threadIdx.x;
    int tx = tid & 15, ty = tid >> 4;
    int ar = tid >> 2, ac = tid & 3;    // A loader: 64 rows x 4 float4
    int br = tid >> 4, bc = tid & 15;   // B loader: 16 rows x 16 float4
    float acc[4][4] = {};

    for (int k0 = 0; k0 < Kk; k0 += 16) {
        float4 av = *(const float4*)&A[(size_t)(m0 + ar) * Kk + k0 + ac * 4];
        As[ac * 4 + 0][ar] = av.x;
        As[ac * 4 + 1][ar] = av.y;
        As[ac * 4 + 2][ar] = av.z;
        As[ac * 4 + 3][ar] = av.w;
        *(float4*)&Bs[br][bc * 4] =
            *(const float4*)&Bb[(size_t)(k0 + br) * Nn + n0 + bc * 4];
        __syncthreads();
        mma_tile(As, Bs, acc, tx, ty);
        __syncthreads();
    }

    float*       Cb = C + (size_t)bz * CH * Nn;
    const float* Rb = resid ? resid + (size_t)bz * CH * Nn : nullptr;
#pragma unroll
    for (int i = 0; i < 4; i++) {
        int m = m0 + ty * 4 + i;
        float bv = bias[m];
#pragma unroll
        for (int j = 0; j < 4; j++) {
            int n = n0 + tx * 4 + j;
            float val = acc[i][j] + bv;
            if (Rb) val += Rb[(size_t)m * Nn + n];
            Cb[(size_t)m * Nn + n] = val;
        }
    }
}

// ---------------- TN GEMM: S[b](n,m) = sum_c Q[b](c,n) * K[b](c,m), scaled --------
__global__ __launch_bounds__(256) void gemm_tn(
    const float* __restrict__ Qm, const float* __restrict__ Km,
    float* __restrict__ S)
{
    int bz = blockIdx.z;
    int m0 = blockIdx.y * 64, n0 = blockIdx.x * 64;
    const float* Qb = Qm + (size_t)bz * CH * NTOK;
    const float* Kb = Km + (size_t)bz * CH * NTOK;

    __shared__ float As[16][68];
    __shared__ float Bs[16][68];
    int tid = threadIdx.x;
    int tx = tid & 15, ty = tid >> 4;
    int br = tid >> 4, bc = tid & 15;
    float acc[4][4] = {};

    for (int k0 = 0; k0 < CH; k0 += 16) {
        *(float4*)&As[br][bc * 4] =
            *(const float4*)&Qb[(size_t)(k0 + br) * NTOK + m0 + bc * 4];
        *(float4*)&Bs[br][bc * 4] =
            *(const float4*)&Kb[(size_t)(k0 + br) * NTOK + n0 + bc * 4];
        __syncthreads();
        mma_tile(As, Bs, acc, tx, ty);
        __syncthreads();
    }

    float* Sb = S + (size_t)bz * NTOK * NTOK;
    const float scale = 0.04419417382415922f; // 512^-0.5
#pragma unroll
    for (int i = 0; i < 4; i++)
#pragma unroll
        for (int j = 0; j < 4; j++)
            Sb[(size_t)(m0 + ty * 4 + i) * NTOK + n0 + tx * 4 + j] = acc[i][j] * scale;
}

// ---------------- row softmax over last dim of S (b, n, 1024) ---------------------
__global__ __launch_bounds__(256) void softmax_rows(float* __restrict__ S)
{
    float* p = S + (size_t)blockIdx.x * NTOK;
    int tid = threadIdx.x;
    float4 v = ((float4*)p)[tid];

    __shared__ float red[256];
    float m = fmaxf(fmaxf(v.x, v.y), fmaxf(v.z, v.w));
    red[tid] = m;
    __syncthreads();
    for (int o = 128; o > 0; o >>= 1) {
        if (tid < o) red[tid] = fmaxf(red[tid], red[tid + o]);
        __syncthreads();
    }
    m = red[0];
    __syncthreads();

    v.x = __expf(v.x - m); v.y = __expf(v.y - m);
    v.z = __expf(v.z - m); v.w = __expf(v.w - m);
    red[tid] = v.x + v.y + v.z + v.w;
    __syncthreads();
    for (int o = 128; o > 0; o >>= 1) {
        if (tid < o) red[tid] += red[tid + o];
        __syncthreads();
    }
    float inv = 1.0f / red[0];
    v.x *= inv; v.y *= inv; v.z *= inv; v.w *= inv;
    ((float4*)p)[tid] = v;
}

// ---------------- NT GEMM: O[b](c,n) = sum_m V[b](c,m) * Attn[b](n,m) -------------
__global__ __launch_bounds__(256) void gemm_nt(
    const float* __restrict__ V, const float* __restrict__ Attn,
    float* __restrict__ O)
{
    int bz = blockIdx.z;
    int m0 = blockIdx.y * 64, n0 = blockIdx.x * 64;
    const float* Vb = V    + (size_t)bz * CH   * NTOK;
    const float* Ab = Attn + (size_t)bz * NTOK * NTOK;

    __shared__ float As[16][68];
    __shared__ float Bs[16][68];
    int tid = threadIdx.x;
    int tx = tid & 15, ty = tid >> 4;
    int ar = tid >> 2, ac = tid & 3;
    float acc[4][4] = {};

    for (int k0 = 0; k0 < NTOK; k0 += 16) {
        float4 av = *(const float4*)&Vb[(size_t)(m0 + ar) * NTOK + k0 + ac * 4];
        As[ac * 4 + 0][ar] = av.x;
        As[ac * 4 + 1][ar] = av.y;
        As[ac * 4 + 2][ar] = av.z;
        As[ac * 4 + 3][ar] = av.w;
        float4 bv = *(const float4*)&Ab[(size_t)(n0 + ar) * NTOK + k0 + ac * 4];
        Bs[ac * 4 + 0][ar] = bv.x;
        Bs[ac * 4 + 1][ar] = bv.y;
        Bs[ac * 4 + 2][ar] = bv.z;
        Bs[ac * 4 + 3][ar] = bv.w;
        __syncthreads();
        mma_tile(As, Bs, acc, tx, ty);
        __syncthreads();
    }

    float* Ob = O + (size_t)bz * CH * NTOK;
#pragma unroll
    for (int i = 0; i < 4; i++)
#pragma unroll
        for (int j = 0; j < 4; j++)
            Ob[(size_t)(m0 + ty * 4 + i) * NTOK + n0 + tx * 4 + j] = acc[i][j];
}

// ---------------- launch ----------------------------------------------------------
extern "C" void kernel_launch(void* const* d_in, const int* in_sizes, int n_in,
                              void* d_out, int out_size)
{
    const float* x     = (const float*)d_in[0];
    const float* gamma = (const float*)d_in[1];
    const float* beta  = (const float*)d_in[2];
    const float* wq    = (const float*)d_in[3];
    const float* bq    = (const float*)d_in[4];
    const float* wk    = (const float*)d_in[5];
    const float* bk    = (const float*)d_in[6];
    const float* wv    = (const float*)d_in[7];
    const float* bv    = (const float*)d_in[8];
    const float* wp    = (const float*)d_in[9];
    const float* bp    = (const float*)d_in[10];
    float* out = (float*)d_out;

    float *hn, *q, *k, *v, *s, *o;
    cudaGetSymbolAddress((void**)&hn, g_hn);
    cudaGetSymbolAddress((void**)&q,  g_q);
    cudaGetSymbolAddress((void**)&k,  g_k);
    cudaGetSymbolAddress((void**)&v,  g_v);
    cudaGetSymbolAddress((void**)&s,  g_s);
    cudaGetSymbolAddress((void**)&o,  g_o);

    // 1. GroupNorm
    groupnorm_kernel<<<BATCH * NGRP, 256>>>(x, gamma, beta, hn);

    // 2. q/k/v projections
    dim3 g_nn(NTOK / 64, CH / 64, BATCH);
    gemm_nn<<<g_nn, 256>>>(wq, hn, bq, nullptr, q);
    gemm_nn<<<g_nn, 256>>>(wk, hn, bk, nullptr, k);
    gemm_nn<<<g_nn, 256>>>(wv, hn, bv, nullptr, v);

    // 3. scores s = q^T k * C^-0.5  (global max subtract is softmax-shift-invariant: skip)
    dim3 g_tn(NTOK / 64, NTOK / 64, BATCH);
    gemm_tn<<<g_tn, 256>>>(q, k, s);

    // 4. softmax over last dim (in place)
    softmax_rows<<<BATCH * NTOK, 256>>>(s);

    // 5. o = v @ attn^T
    gemm_nt<<<g_nn, 256>>>(v, s, o);

    // 6. proj + bias + residual -> output
    gemm_nn<<<g_nn, 256>>>(wp, o, bp, x, out);
}

// round 6
// speedup vs baseline: 3.0271x; 3.0271x over previous
#include <cuda_runtime.h>
#include <cstdint>

#define BATCH 32
#define CH    512
#define NGRP  16
#define CPG   32
#define NTOK  1024
#define GSIZE (CPG * NTOK)

// ---------------- scratch (static device globals; runtime alloc is forbidden) ----
__device__ float g_hn[(size_t)BATCH * CH * NTOK];
__device__ float g_q [(size_t)BATCH * CH * NTOK];
__device__ float g_k [(size_t)BATCH * CH * NTOK];
__device__ float g_v [(size_t)BATCH * CH * NTOK];
__device__ float g_s [(size_t)BATCH * NTOK * NTOK];
__device__ float g_o [(size_t)BATCH * CH * NTOK];

// ---------------- GroupNorm -------------------------------------------------------
__global__ __launch_bounds__(256) void groupnorm_kernel(
    const float* __restrict__ x, const float* __restrict__ gamma,
    const float* __restrict__ beta, float* __restrict__ hn)
{
    int b = blockIdx.x / NGRP;
    int g = blockIdx.x % NGRP;
    const float* xp = x  + ((size_t)b * CH + g * CPG) * NTOK;
    float*       hp = hn + ((size_t)b * CH + g * CPG) * NTOK;
    int tid = threadIdx.x;

    float s = 0.f, s2 = 0.f;
    for (int i = tid; i < GSIZE; i += 256) {
        float v = xp[i];
        s += v; s2 += v * v;
    }
    __shared__ float rs[256], rs2[256];
    rs[tid] = s; rs2[tid] = s2;
    __syncthreads();
    for (int o = 128; o > 0; o >>= 1) {
        if (tid < o) { rs[tid] += rs[tid + o]; rs2[tid] += rs2[tid + o]; }
        __syncthreads();
    }
    float mean = rs[0] * (1.0f / GSIZE);
    float var  = rs2[0] * (1.0f / GSIZE) - mean * mean;
    float rstd = rsqrtf(var + 1e-6f);

    for (int i = tid; i < GSIZE; i += 256) {
        int c = g * CPG + i / NTOK;
        hp[i] = (xp[i] - mean) * rstd * gamma[c] + beta[c];
    }
}

// ---------------- tf32 helpers ----------------------------------------------------
__device__ __forceinline__ float tf32r(float x) {
    uint32_t u;
    asm("cvt.rna.tf32.f32 %0, %1;" : "=r"(u) : "f"(x));
    return __uint_as_float(u);
}
__device__ __forceinline__ float4 tf32x4(float4 v) {
    v.x = tf32r(v.x); v.y = tf32r(v.y); v.z = tf32r(v.z); v.w = tf32r(v.w);
    return v;
}
__device__ __forceinline__ void mma8(float c[4],
    uint32_t a0, uint32_t a1, uint32_t a2, uint32_t a3, uint32_t b0, uint32_t b1)
{
    asm volatile(
        "mma.sync.aligned.m16n8k8.row.col.f32.tf32.tf32.f32 "
        "{%0,%1,%2,%3}, {%4,%5,%6,%7}, {%8,%9}, {%0,%1,%2,%3};"
        : "+f"(c[0]), "+f"(c[1]), "+f"(c[2]), "+f"(c[3])
        : "r"(a0), "r"(a1), "r"(a2), "r"(a3), "r"(b0), "r"(b1));
}
__device__ __forceinline__ uint32_t fbits(float x) { return __float_as_uint(x); }

// ---------------- tensor-core batched GEMM ---------------------------------------
// C[bz](M x N) = A * B (+bias(+resid)), scaled. Block tile 128x128, k-step 16.
// TA: A given row-major [M][K] (needs transpose to k-major)  else A is [K][M].
// TB: B given row-major [N][K] (transpose)                   else B is [K][N].
// SMEM layouts: k-major slab [16][136] (direct), m-major slab [128][20] (trans).
template<bool TA, bool TB>
__global__ __launch_bounds__(256, 2) void gemm_mma(
    const float* __restrict__ A, const float* __restrict__ B,
    const float* __restrict__ bias, const float* __restrict__ resid,
    float* __restrict__ C,
    int K, int lda, int ldb, int ldc,
    long strideA, long strideB, long strideC, float scale)
{
    __shared__ float SA[2560];   // max(16*136, 128*20)
    __shared__ float SB[2560];

    const int bz = blockIdx.z;
    const int m0 = blockIdx.y * 128, n0 = blockIdx.x * 128;
    const float* Ab = A + (size_t)bz * strideA;
    const float* Bb = B + (size_t)bz * strideB;

    const int tid  = threadIdx.x;
    const int lane = tid & 31, warp = tid >> 5;
    const int wm = warp >> 1, wn = warp & 1;      // 4 x 2 warp grid
    const int g  = lane >> 2, tg = lane & 3;      // groupID, threadID_in_group

    float acc[2][8][4];
#pragma unroll
    for (int i = 0; i < 2; i++)
#pragma unroll
        for (int j = 0; j < 8; j++)
#pragma unroll
            for (int c = 0; c < 4; c++) acc[i][j][c] = 0.f;

    // ---- slab load / store helpers (2 float4 per thread per operand) ----
    auto loadA = [&](float4 va[2], int k0) {
#pragma unroll
        for (int i = 0; i < 2; i++) {
            int idx = tid + i * 256;
            if (TA) { int m = idx >> 2, k4 = idx & 3;
                      va[i] = *(const float4*)&Ab[(size_t)(m0 + m) * lda + k0 + k4 * 4]; }
            else    { int k = idx >> 5, m4 = idx & 31;
                      va[i] = *(const float4*)&Ab[(size_t)(k0 + k) * lda + m0 + m4 * 4]; }
        }
    };
    auto loadB = [&](float4 vb[2], int k0) {
#pragma unroll
        for (int i = 0; i < 2; i++) {
            int idx = tid + i * 256;
            if (TB) { int n = idx >> 2, k4 = idx & 3;
                      vb[i] = *(const float4*)&Bb[(size_t)(n0 + n) * ldb + k0 + k4 * 4]; }
            else    { int k = idx >> 5, n4 = idx & 31;
                      vb[i] = *(const float4*)&Bb[(size_t)(k0 + k) * ldb + n0 + n4 * 4]; }
        }
    };
    auto storeA = [&](const float4 va[2]) {
#pragma unroll
        for (int i = 0; i < 2; i++) {
            int idx = tid + i * 256;
            if (TA) { int m = idx >> 2, k4 = idx & 3;
                      *(float4*)&SA[m * 20 + k4 * 4] = tf32x4(va[i]); }
            else    { int k = idx >> 5, m4 = idx & 31;
                      *(float4*)&SA[k * 136 + m4 * 4] = tf32x4(va[i]); }
        }
    };
    auto storeB = [&](const float4 vb[2]) {
#pragma unroll
        for (int i = 0; i < 2; i++) {
            int idx = tid + i * 256;
            if (TB) { int n = idx >> 2, k4 = idx & 3;
                      *(float4*)&SB[n * 20 + k4 * 4] = tf32x4(vb[i]); }
            else    { int k = idx >> 5, n4 = idx & 31;
                      *(float4*)&SB[k * 136 + n4 * 4] = tf32x4(vb[i]); }
        }
    };

    // ---- pipelined main loop ----
    {
        float4 va[2], vb[2];
        loadA(va, 0); loadB(vb, 0);
        storeA(va);   storeB(vb);
    }
    __syncthreads();

    for (int k0 = 0; k0 < K; k0 += 16) {
        const bool nxt = (k0 + 16) < K;
        float4 na[2], nb[2];
        if (nxt) { loadA(na, k0 + 16); loadB(nb, k0 + 16); }

#pragma unroll
        for (int kk = 0; kk < 16; kk += 8) {
            uint32_t a0[2], a1[2], a2[2], a3[2];
#pragma unroll
            for (int mi = 0; mi < 2; mi++) {
                int mb = wm * 32 + mi * 16;
                if (TA) {
                    a0[mi] = fbits(SA[(mb + g)     * 20 + kk + tg]);
                    a1[mi] = fbits(SA[(mb + 8 + g) * 20 + kk + tg]);
                    a2[mi] = fbits(SA[(mb + g)     * 20 + kk + tg + 4]);
                    a3[mi] = fbits(SA[(mb + 8 + g) * 20 + kk + tg + 4]);
                } else {
                    a0[mi] = fbits(SA[(kk + tg)     * 136 + mb + g]);
                    a1[mi] = fbits(SA[(kk + tg)     * 136 + mb + 8 + g]);
                    a2[mi] = fbits(SA[(kk + tg + 4) * 136 + mb + g]);
                    a3[mi] = fbits(SA[(kk + tg + 4) * 136 + mb + 8 + g]);
                }
            }
#pragma unroll
            for (int ni = 0; ni < 8; ni++) {
                int nb2 = wn * 64 + ni * 8;
                uint32_t b0, b1;
                if (TB) {
                    b0 = fbits(SB[(nb2 + g) * 20 + kk + tg]);
                    b1 = fbits(SB[(nb2 + g) * 20 + kk + tg + 4]);
                } else {
                    b0 = fbits(SB[(kk + tg)     * 136 + nb2 + g]);
                    b1 = fbits(SB[(kk + tg + 4) * 136 + nb2 + g]);
                }
                mma8(acc[0][ni], a0[0], a1[0], a2[0], a3[0], b0, b1);
                mma8(acc[1][ni], a0[1], a1[1], a2[1], a3[1], b0, b1);
            }
        }

        if (nxt) {
            __syncthreads();
            storeA(na); storeB(nb);
            __syncthreads();
        }
    }

    // ---- epilogue ----
    float*       Cb = C + (size_t)bz * strideC;
    const float* Rb = resid ? resid + (size_t)bz * strideC : nullptr;
#pragma unroll
    for (int mi = 0; mi < 2; mi++) {
#pragma unroll
        for (int half = 0; half < 2; half++) {
            int m = m0 + wm * 32 + mi * 16 + g + half * 8;
            float bv = bias ? bias[m] : 0.f;
#pragma unroll
            for (int ni = 0; ni < 8; ni++) {
                int n = n0 + wn * 64 + ni * 8 + tg * 2;
                float2 val;
                val.x = acc[mi][ni][half * 2 + 0] * scale + bv;
                val.y = acc[mi][ni][half * 2 + 1] * scale + bv;
                if (Rb) {
                    val.x += Rb[(size_t)m * ldc + n];
                    val.y += Rb[(size_t)m * ldc + n + 1];
                }
                *(float2*)&Cb[(size_t)m * ldc + n] = val;
            }
        }
    }
}

// ---------------- row softmax over last dim of S (b*n rows of 1024) ---------------
__global__ __launch_bounds__(256) void softmax_rows(float* __restrict__ S)
{
    float* p = S + (size_t)blockIdx.x * NTOK;
    int tid = threadIdx.x;
    float4 v = ((float4*)p)[tid];

    __shared__ float red[256];
    float m = fmaxf(fmaxf(v.x, v.y), fmaxf(v.z, v.w));
    red[tid] = m;
    __syncthreads();
    for (int o = 128; o > 0; o >>= 1) {
        if (tid < o) red[tid] = fmaxf(red[tid], red[tid + o]);
        __syncthreads();
    }
    m = red[0];
    __syncthreads();

    v.x = __expf(v.x - m); v.y = __expf(v.y - m);
    v.z = __expf(v.z - m); v.w = __expf(v.w - m);
    red[tid] = v.x + v.y + v.z + v.w;
    __syncthreads();
    for (int o = 128; o > 0; o >>= 1) {
        if (tid < o) red[tid] += red[tid + o];
        __syncthreads();
    }
    float inv = 1.0f / red[0];
    v.x *= inv; v.y *= inv; v.z *= inv; v.w *= inv;
    ((float4*)p)[tid] = v;
}

// ---------------- launch ----------------------------------------------------------
extern "C" void kernel_launch(void* const* d_in, const int* in_sizes, int n_in,
                              void* d_out, int out_size)
{
    const float* x     = (const float*)d_in[0];
    const float* gamma = (const float*)d_in[1];
    const float* beta  = (const float*)d_in[2];
    const float* wq    = (const float*)d_in[3];
    const float* bq    = (const float*)d_in[4];
    const float* wk    = (const float*)d_in[5];
    const float* bk    = (const float*)d_in[6];
    const float* wv    = (const float*)d_in[7];
    const float* bv    = (const float*)d_in[8];
    const float* wp    = (const float*)d_in[9];
    const float* bp    = (const float*)d_in[10];
    float* out = (float*)d_out;

    float *hn, *q, *k, *v, *s, *o;
    cudaGetSymbolAddress((void**)&hn, g_hn);
    cudaGetSymbolAddress((void**)&q,  g_q);
    cudaGetSymbolAddress((void**)&k,  g_k);
    cudaGetSymbolAddress((void**)&v,  g_v);
    cudaGetSymbolAddress((void**)&s,  g_s);
    cudaGetSymbolAddress((void**)&o,  g_o);

    const long sBN = (long)CH * NTOK;    // per-batch stride for (c, n) tensors
    const long sS  = (long)NTOK * NTOK;  // per-batch stride for scores

    // 1. GroupNorm
    groupnorm_kernel<<<BATCH * NGRP, 256>>>(x, gamma, beta, hn);

    // 2. q/k/v projections: C(512x1024) = W(512x512, row-major -> TA) * hn(k-major)
    dim3 g_nn(NTOK / 128, CH / 128, BATCH);
    gemm_mma<true,  false><<<g_nn, 256>>>(wq, hn, bq, nullptr, q,
        CH, CH, NTOK, NTOK, 0, sBN, sBN, 1.0f);
    gemm_mma<true,  false><<<g_nn, 256>>>(wk, hn, bk, nullptr, k,
        CH, CH, NTOK, NTOK, 0, sBN, sBN, 1.0f);
    gemm_mma<true,  false><<<g_nn, 256>>>(wv, hn, bv, nullptr, v,
        CH, CH, NTOK, NTOK, 0, sBN, sBN, 1.0f);

    // 3. scores S(1024x1024) = q^T k * C^-0.5 : both operands already k(=c)-major
    dim3 g_tn(NTOK / 128, NTOK / 128, BATCH);
    gemm_mma<false, false><<<g_tn, 256>>>(q, k, nullptr, nullptr, s,
        CH, NTOK, NTOK, NTOK, sBN, sBN, sS, 0.04419417382415922f);

    // 4. softmax over last dim (in place)
    softmax_rows<<<BATCH * NTOK, 256>>>(s);

    // 5. O(512x1024) = V(c x m, row-major -> TA) * attn^T(n x m, row-major -> TB)
    gemm_mma<true,  true ><<<g_nn, 256>>>(v, s, nullptr, nullptr, o,
        NTOK, NTOK, NTOK, NTOK, sBN, sS, sBN, 1.0f);

    // 6. proj + bias + residual -> out
    gemm_mma<true,  false><<<g_nn, 256>>>(wp, o, bp, x, out,
        CH, CH, NTOK, NTOK, 0, sBN, sBN, 1.0f);
}

// round 10
// speedup vs baseline: 3.4967x; 1.1551x over previous
#include <cuda_runtime.h>
#include <cstdint>

#define BATCH 32
#define CH    512
#define NGRP  16
#define CPG   32
#define NTOK  1024
#define GSIZE (CPG * NTOK)

#define STAGES 4
#define STG    10240                       // bytes per operand stage (max of 16*136*4, 128*20*4)
#define SMEM_TOTAL (2 * STAGES * STG)      // 81920 B

// ---------------- scratch (static device globals; runtime alloc forbidden) -------
__device__ float g_hn[(size_t)BATCH * CH * NTOK];   // (b, c, n) channel-major, tf32
__device__ float g_q [(size_t)BATCH * CH * NTOK];
__device__ float g_k [(size_t)BATCH * CH * NTOK];
__device__ float g_v [(size_t)BATCH * CH * NTOK];
__device__ float g_s [(size_t)BATCH * NTOK * NTOK];
__device__ float g_o [(size_t)BATCH * CH * NTOK];
__device__ float g_w [4 * CH * CH];                 // tf32-rounded weights

// ---------------- helpers ---------------------------------------------------------
__device__ __forceinline__ uint32_t smem_u32(const void* p) {
    uint32_t a;
    asm("{ .reg .u64 t; cvta.to.shared.u64 t, %1; cvt.u32.u64 %0, t; }" : "=r"(a) : "l"(p));
    return a;
}
__device__ __forceinline__ float tf32r(float x) {
    uint32_t u;
    asm("cvt.rna.tf32.f32 %0, %1;" : "=r"(u) : "f"(x));
    return __uint_as_float(u);
}
__device__ __forceinline__ float4 tf32x4(float4 v) {
    v.x = tf32r(v.x); v.y = tf32r(v.y); v.z = tf32r(v.z); v.w = tf32r(v.w);
    return v;
}
__device__ __forceinline__ void cpa16(uint32_t s, const void* g) {
    asm volatile("cp.async.cg.shared.global [%0], [%1], 16;" :: "r"(s), "l"(g));
}
__device__ __forceinline__ void mma8(float c[4],
    uint32_t a0, uint32_t a1, uint32_t a2, uint32_t a3, uint32_t b0, uint32_t b1)
{
    asm volatile(
        "mma.sync.aligned.m16n8k8.row.col.f32.tf32.tf32.f32 "
        "{%0,%1,%2,%3}, {%4,%5,%6,%7}, {%8,%9}, {%0,%1,%2,%3};"
        : "+f"(c[0]), "+f"(c[1]), "+f"(c[2]), "+f"(c[3])
        : "r"(a0), "r"(a1), "r"(a2), "r"(a3), "r"(b0), "r"(b1));
}
__device__ __forceinline__ uint32_t fbits(float x) { return __float_as_uint(x); }

// ---------------- weight rounding to tf32 -----------------------------------------
__global__ __launch_bounds__(256) void roundw_kernel(const float* __restrict__ w,
                                                     float* __restrict__ dst) {
    int i = blockIdx.x * 256 + threadIdx.x;   // CH*CH/4 float4s
    ((float4*)dst)[i] = tf32x4(((const float4*)w)[i]);
}

// ---------------- GroupNorm (channel-major out, tf32-rounded) ---------------------
__global__ __launch_bounds__(256) void groupnorm_kernel(
    const float* __restrict__ x, const float* __restrict__ gamma,
    const float* __restrict__ beta, float* __restrict__ hn)
{
    int b = blockIdx.x / NGRP;
    int g = blockIdx.x % NGRP;
    const float* xp = x  + ((size_t)b * CH + g * CPG) * NTOK;
    float*       hp = hn + ((size_t)b * CH + g * CPG) * NTOK;
    int tid = threadIdx.x;

    float s = 0.f, s2 = 0.f;
    for (int i = tid; i < GSIZE; i += 256) {
        float v = xp[i];
        s += v; s2 += v * v;
    }
    __shared__ float rs[256], rs2[256];
    rs[tid] = s; rs2[tid] = s2;
    __syncthreads();
    for (int o = 128; o > 0; o >>= 1) {
        if (tid < o) { rs[tid] += rs[tid + o]; rs2[tid] += rs2[tid + o]; }
        __syncthreads();
    }
    float mean = rs[0] * (1.0f / GSIZE);
    float var  = rs2[0] * (1.0f / GSIZE) - mean * mean;
    float rstd = rsqrtf(var + 1e-6f);

    for (int i = tid * 4; i < GSIZE; i += 1024) {
        int c = g * CPG + i / NTOK;
        float gm = gamma[c], bt = beta[c];
        float4 v = *(const float4*)&xp[i];
        v.x = tf32r((v.x - mean) * rstd * gm + bt);
        v.y = tf32r((v.y - mean) * rstd * gm + bt);
        v.z = tf32r((v.z - mean) * rstd * gm + bt);
        v.w = tf32r((v.w - mean) * rstd * gm + bt);
        *(float4*)&hp[i] = v;
    }
}

// ---------------- tf32 mma.sync batched GEMM, cp.async 4-stage pipeline ------------
// C[bz](M x N) = A * B (*scale +bias(+resid)). Block tile 128x128, k-step 16.
// TA: A row-major [M][K] -> SMEM m-major [128][20]; else [K][M] -> k-major [16][136].
// TB: B row-major [N][K] -> SMEM m-major;            else [K][N] -> k-major.
// All inputs must already be tf32-rounded in gmem (raw cp.async copies).
template<bool TA, bool TB>
__global__ __launch_bounds__(256, 2) void gemm_cp(
    const float* __restrict__ A, long strideA, int lda,
    const float* __restrict__ B, long strideB, int ldb,
    float* __restrict__ C, long strideC, int ldc,
    int K, const float* __restrict__ bias, const float* __restrict__ resid,
    float scale, int roundOut)
{
    extern __shared__ char smem[];
    const uint32_t sbase = smem_u32(smem);

    const int bz = blockIdx.z;
    const int m0 = blockIdx.y * 128, n0 = blockIdx.x * 128;
    const float* Ab = A + (size_t)bz * strideA;
    const float* Bb = B + (size_t)bz * strideB;

    const int tid  = threadIdx.x;
    const int lane = tid & 31, warp = tid >> 5;
    const int wm = warp >> 1, wn = warp & 1;      // 4 x 2 warp grid (32 x 64 tiles)
    const int g  = lane >> 2, tg = lane & 3;

    float acc[2][8][4];
#pragma unroll
    for (int i = 0; i < 2; i++)
#pragma unroll
        for (int j = 0; j < 8; j++)
#pragma unroll
            for (int c = 0; c < 4; c++) acc[i][j][c] = 0.f;

    const int nsteps = K / 16;

    auto issue = [&](int step) {
        const int s = step & (STAGES - 1);
        const uint32_t sa  = sbase + s * STG;
        const uint32_t sbb = sbase + STAGES * STG + s * STG;
        const int k0 = step * 16;
#pragma unroll
        for (int i = 0; i < 2; i++) {
            int idx = tid + i * 256;
            if (TA) { int m = idx >> 2, kq = idx & 3;
                cpa16(sa + m * 80 + kq * 16,
                      Ab + (size_t)(m0 + m) * lda + k0 + kq * 4); }
            else    { int kk = idx >> 5, m4 = idx & 31;
                cpa16(sa + kk * 544 + m4 * 16,
                      Ab + (size_t)(k0 + kk) * lda + m0 + m4 * 4); }
        }
#pragma unroll
        for (int i = 0; i < 2; i++) {
            int idx = tid + i * 256;
            if (TB) { int n = idx >> 2, kq = idx & 3;
                cpa16(sbb + n * 80 + kq * 16,
                      Bb + (size_t)(n0 + n) * ldb + k0 + kq * 4); }
            else    { int kk = idx >> 5, n4 = idx & 31;
                cpa16(sbb + kk * 544 + n4 * 16,
                      Bb + (size_t)(k0 + kk) * ldb + n0 + n4 * 4); }
        }
        asm volatile("cp.async.commit_group;" ::: "memory");
    };

    // prologue: STAGES-1 groups in flight
#pragma unroll
    for (int p = 0; p < STAGES - 1; p++) issue(p);

    for (int t = 0; t < nsteps; t++) {
        asm volatile("cp.async.wait_group %0;" :: "n"(STAGES - 2) : "memory");
        __syncthreads();
        if (t + STAGES - 1 < nsteps) issue(t + STAGES - 1);
        else asm volatile("cp.async.commit_group;" ::: "memory");

        const float* SA = (const float*)(smem + (size_t)(t & (STAGES - 1)) * STG);
        const float* SB = (const float*)(smem + (size_t)STAGES * STG
                                              + (size_t)(t & (STAGES - 1)) * STG);
#pragma unroll
        for (int kk = 0; kk < 16; kk += 8) {
            uint32_t a0[2], a1[2], a2[2], a3[2];
#pragma unroll
            for (int mi = 0; mi < 2; mi++) {
                int mb = wm * 32 + mi * 16;
                if (TA) {
                    a0[mi] = fbits(SA[(mb + g)     * 20 + kk + tg]);
                    a1[mi] = fbits(SA[(mb + 8 + g) * 20 + kk + tg]);
                    a2[mi] = fbits(SA[(mb + g)     * 20 + kk + tg + 4]);
                    a3[mi] = fbits(SA[(mb + 8 + g) * 20 + kk + tg + 4]);
                } else {
                    a0[mi] = fbits(SA[(kk + tg)     * 136 + mb + g]);
                    a1[mi] = fbits(SA[(kk + tg)     * 136 + mb + 8 + g]);
                    a2[mi] = fbits(SA[(kk + tg + 4) * 136 + mb + g]);
                    a3[mi] = fbits(SA[(kk + tg + 4) * 136 + mb + 8 + g]);
                }
            }
#pragma unroll
            for (int ni = 0; ni < 8; ni++) {
                int nb2 = wn * 64 + ni * 8;
                uint32_t b0, b1;
                if (TB) {
                    b0 = fbits(SB[(nb2 + g) * 20 + kk + tg]);
                    b1 = fbits(SB[(nb2 + g) * 20 + kk + tg + 4]);
                } else {
                    b0 = fbits(SB[(kk + tg)     * 136 + nb2 + g]);
                    b1 = fbits(SB[(kk + tg + 4) * 136 + nb2 + g]);
                }
                mma8(acc[0][ni], a0[0], a1[0], a2[0], a3[0], b0, b1);
                mma8(acc[1][ni], a0[1], a1[1], a2[1], a3[1], b0, b1);
            }
        }
    }

    // ---- epilogue ----
    float*       Cb = C + (size_t)bz * strideC;
    const float* Rb = resid ? resid + (size_t)bz * strideC : nullptr;
#pragma unroll
    for (int mi = 0; mi < 2; mi++) {
#pragma unroll
        for (int half = 0; half < 2; half++) {
            int m = m0 + wm * 32 + mi * 16 + g + half * 8;
            float bv = bias ? bias[m] : 0.f;
#pragma unroll
            for (int ni = 0; ni < 8; ni++) {
                int n = n0 + wn * 64 + ni * 8 + tg * 2;
                float2 val;
                val.x = acc[mi][ni][half * 2 + 0] * scale + bv;
                val.y = acc[mi][ni][half * 2 + 1] * scale + bv;
                if (Rb) {
                    val.x += Rb[(size_t)m * ldc + n];
                    val.y += Rb[(size_t)m * ldc + n + 1];
                }
                if (roundOut) { val.x = tf32r(val.x); val.y = tf32r(val.y); }
                *(float2*)&Cb[(size_t)m * ldc + n] = val;
            }
        }
    }
}

// ---------------- row softmax, tf32-rounded output --------------------------------
__global__ __launch_bounds__(256) void softmax_rows(float* __restrict__ S)
{
    float* p = S + (size_t)blockIdx.x * NTOK;
    int tid = threadIdx.x;
    float4 v = ((float4*)p)[tid];

    __shared__ float red[256];
    float m = fmaxf(fmaxf(v.x, v.y), fmaxf(v.z, v.w));
    red[tid] = m;
    __syncthreads();
    for (int o = 128; o > 0; o >>= 1) {
        if (tid < o) red[tid] = fmaxf(red[tid], red[tid + o]);
        __syncthreads();
    }
    m = red[0];
    __syncthreads();

    v.x = __expf(v.x - m); v.y = __expf(v.y - m);
    v.z = __expf(v.z - m); v.w = __expf(v.w - m);
    red[tid] = v.x + v.y + v.z + v.w;
    __syncthreads();
    for (int o = 128; o > 0; o >>= 1) {
        if (tid < o) red[tid] += red[tid + o];
        __syncthreads();
    }
    float inv = 1.0f / red[0];
    v.x = tf32r(v.x * inv); v.y = tf32r(v.y * inv);
    v.z = tf32r(v.z * inv); v.w = tf32r(v.w * inv);
    ((float4*)p)[tid] = v;
}

// ---------------- launch ----------------------------------------------------------
extern "C" void kernel_launch(void* const* d_in, const int* in_sizes, int n_in,
                              void* d_out, int out_size)
{
    const float* x     = (const float*)d_in[0];
    const float* gamma = (const float*)d_in[1];
    const float* beta  = (const float*)d_in[2];
    const float* wq    = (const float*)d_in[3];
    const float* bq    = (const float*)d_in[4];
    const float* wk    = (const float*)d_in[5];
    const float* bk    = (const float*)d_in[6];
    const float* wv    = (const float*)d_in[7];
    const float* bv    = (const float*)d_in[8];
    const float* wp    = (const float*)d_in[9];
    const float* bp    = (const float*)d_in[10];
    float* out = (float*)d_out;

    float *hn, *q, *k, *v, *s, *o, *w;
    cudaGetSymbolAddress((void**)&hn, g_hn);
    cudaGetSymbolAddress((void**)&q,  g_q);
    cudaGetSymbolAddress((void**)&k,  g_k);
    cudaGetSymbolAddress((void**)&v,  g_v);
    cudaGetSymbolAddress((void**)&s,  g_s);
    cudaGetSymbolAddress((void**)&o,  g_o);
    cudaGetSymbolAddress((void**)&w,  g_w);

    cudaFuncSetAttribute(gemm_cp<true,  false>, cudaFuncAttributeMaxDynamicSharedMemorySize, SMEM_TOTAL);
    cudaFuncSetAttribute(gemm_cp<false, false>, cudaFuncAttributeMaxDynamicSharedMemorySize, SMEM_TOTAL);
    cudaFuncSetAttribute(gemm_cp<true,  true >, cudaFuncAttributeMaxDynamicSharedMemorySize, SMEM_TOTAL);

    const long sBN = (long)CH * NTOK;
    const long sS  = (long)NTOK * NTOK;

    // 0. round weights to tf32
    roundw_kernel<<<CH * CH / 1024, 256>>>(wq, w + 0 * CH * CH);
    roundw_kernel<<<CH * CH / 1024, 256>>>(wk, w + 1 * CH * CH);
    roundw_kernel<<<CH * CH / 1024, 256>>>(wv, w + 2 * CH * CH);
    roundw_kernel<<<CH * CH / 1024, 256>>>(wp, w + 3 * CH * CH);

    // 1. GroupNorm -> hn (channel-major, tf32)
    groupnorm_kernel<<<BATCH * NGRP, 256>>>(x, gamma, beta, hn);

    // 2. q/k/v: C(512x1024) = W(row-major, TA) x hn(k-major)
    dim3 g_nn(NTOK / 128, CH / 128, BATCH);
    gemm_cp<true,  false><<<g_nn, 256, SMEM_TOTAL>>>(
        w + 0 * CH * CH, 0, CH,  hn, sBN, NTOK,  q, sBN, NTOK,
        CH, bq, nullptr, 1.0f, 1);
    gemm_cp<true,  false><<<g_nn, 256, SMEM_TOTAL>>>(
        w + 1 * CH * CH, 0, CH,  hn, sBN, NTOK,  k, sBN, NTOK,
        CH, bk, nullptr, 1.0f, 1);
    gemm_cp<true,  false><<<g_nn, 256, SMEM_TOTAL>>>(
        w + 2 * CH * CH, 0, CH,  hn, sBN, NTOK,  v, sBN, NTOK,
        CH, bv, nullptr, 1.0f, 1);

    // 3. scores S(n,m) = q^T k * C^-0.5 (both k(=c)-major)
    dim3 g_tn(NTOK / 128, NTOK / 128, BATCH);
    gemm_cp<false, false><<<g_tn, 256, SMEM_TOTAL>>>(
        q, sBN, NTOK,  k, sBN, NTOK,  s, sS, NTOK,
        CH, nullptr, nullptr, 0.04419417382415922f, 0);

    // 4. softmax (in place, tf32 out)
    softmax_rows<<<BATCH * NTOK, 256>>>(s);

    // 5. O(c,n) = V(c,m; TA) x attn^T(n,m; TB), K = 1024
    gemm_cp<true,  true ><<<g_nn, 256, SMEM_TOTAL>>>(
        v, sBN, NTOK,  s, sS, NTOK,  o, sBN, NTOK,
        NTOK, nullptr, nullptr, 1.0f, 1);

    // 6. out = Wp x o + bp + x
    gemm_cp<true,  false><<<g_nn, 256, SMEM_TOTAL>>>(
        w + 3 * CH * CH, 0, CH,  o, sBN, NTOK,  out, sBN, NTOK,
        CH, bp, x, 1.0f, 0);
}

// round 11
// speedup vs baseline: 3.5802x; 1.0239x over previous
#include <cuda_runtime.h>
#include <cstdint>

#define BATCH 32
#define CH    512
#define NGRP  16
#define CPG   32
#define NTOK  1024
#define GSIZE (CPG * NTOK)

#define STAGES 4
#define STG    10240                       // bytes per operand stage (max of 16*136*4, 128*20*4)
#define SMEM_TOTAL (2 * STAGES * STG)      // 81920 B

// ---------------- scratch (static device globals; runtime alloc forbidden) -------
__device__ float g_hn [(size_t)BATCH * CH * NTOK];      // (b, c, n) channel-major, tf32
__device__ float g_qkv[(size_t)BATCH * 3 * CH * NTOK];  // (b, {q,k,v}, c, n), tf32
__device__ float g_s  [(size_t)BATCH * NTOK * NTOK];
__device__ float g_o  [(size_t)BATCH * CH * NTOK];
__device__ float g_w  [4 * CH * CH];                    // tf32-rounded wq|wk|wv|wp
__device__ float g_bqkv[3 * CH];                        // stacked bq|bk|bv

// ---------------- helpers ---------------------------------------------------------
__device__ __forceinline__ float tf32r(float x) {
    uint32_t u;
    asm("cvt.rna.tf32.f32 %0, %1;" : "=r"(u) : "f"(x));
    return __uint_as_float(u);
}
__device__ __forceinline__ float4 tf32x4(float4 v) {
    v.x = tf32r(v.x); v.y = tf32r(v.y); v.z = tf32r(v.z); v.w = tf32r(v.w);
    return v;
}
__device__ __forceinline__ void cpa16(uint32_t s, const void* g) {
    asm volatile("cp.async.cg.shared.global [%0], [%1], 16;" :: "r"(s), "l"(g));
}
__device__ __forceinline__ uint32_t smem_u32(const void* p) {
    uint32_t a;
    asm("{ .reg .u64 t; cvta.to.shared.u64 t, %1; cvt.u32.u64 %0, t; }" : "=r"(a) : "l"(p));
    return a;
}
__device__ __forceinline__ void mma8(float c[4],
    uint32_t a0, uint32_t a1, uint32_t a2, uint32_t a3, uint32_t b0, uint32_t b1)
{
    asm volatile(
        "mma.sync.aligned.m16n8k8.row.col.f32.tf32.tf32.f32 "
        "{%0,%1,%2,%3}, {%4,%5,%6,%7}, {%8,%9}, {%0,%1,%2,%3};"
        : "+f"(c[0]), "+f"(c[1]), "+f"(c[2]), "+f"(c[3])
        : "r"(a0), "r"(a1), "r"(a2), "r"(a3), "r"(b0), "r"(b1));
}
__device__ __forceinline__ uint32_t fbits(float x) { return __float_as_uint(x); }

// ---------------- setup: round 4 weight matrices to tf32 --------------------------
__global__ __launch_bounds__(256) void round_weights(
    const float* __restrict__ wq, const float* __restrict__ wk,
    const float* __restrict__ wv, const float* __restrict__ wp,
    float* __restrict__ w)
{
    int i = blockIdx.x * 256 + threadIdx.x;   // 4 * 65536 float4s
    int m = i >> 16, j = i & 65535;
    const float* src = (m == 0) ? wq : (m == 1) ? wk : (m == 2) ? wv : wp;
    ((float4*)(w + (size_t)m * CH * CH))[j] = tf32x4(((const float4*)src)[j]);
}
__global__ __launch_bounds__(512) void stack_bias(
    const float* __restrict__ bq, const float* __restrict__ bk,
    const float* __restrict__ bv, float* __restrict__ dst)
{
    int i = threadIdx.x;
    dst[i] = bq[i]; dst[CH + i] = bk[i]; dst[2 * CH + i] = bv[i];
}

// ---------------- GroupNorm (channel-major out, tf32-rounded) ---------------------
__global__ __launch_bounds__(256) void groupnorm_kernel(
    const float* __restrict__ x, const float* __restrict__ gamma,
    const float* __restrict__ beta, float* __restrict__ hn)
{
    int b = blockIdx.x / NGRP;
    int g = blockIdx.x % NGRP;
    const float* xp = x  + ((size_t)b * CH + g * CPG) * NTOK;
    float*       hp = hn + ((size_t)b * CH + g * CPG) * NTOK;
    int tid = threadIdx.x;

    float s = 0.f, s2 = 0.f;
    for (int i = tid; i < GSIZE; i += 256) {
        float v = xp[i];
        s += v; s2 += v * v;
    }
    __shared__ float rs[256], rs2[256];
    rs[tid] = s; rs2[tid] = s2;
    __syncthreads();
    for (int o = 128; o > 0; o >>= 1) {
        if (tid < o) { rs[tid] += rs[tid + o]; rs2[tid] += rs2[tid + o]; }
        __syncthreads();
    }
    float mean = rs[0] * (1.0f / GSIZE);
    float var  = rs2[0] * (1.0f / GSIZE) - mean * mean;
    float rstd = rsqrtf(var + 1e-6f);

    for (int i = tid * 4; i < GSIZE; i += 1024) {
        int c = g * CPG + i / NTOK;
        float gm = gamma[c], bt = beta[c];
        float4 v = *(const float4*)&xp[i];
        v.x = tf32r((v.x - mean) * rstd * gm + bt);
        v.y = tf32r((v.y - mean) * rstd * gm + bt);
        v.z = tf32r((v.z - mean) * rstd * gm + bt);
        v.w = tf32r((v.w - mean) * rstd * gm + bt);
        *(float4*)&hp[i] = v;
    }
}

// ---------------- tf32 mma.sync batched GEMM, cp.async pipeline + frag prefetch ----
// C[bz](M x N) = A * B (*scale +bias(+resid)). Block tile 128x128, k-step 16.
// TA: A row-major [M][K] -> SMEM m-major [128][20]; else [K][M] -> k-major [16][136].
// TB: B row-major [N][K] -> SMEM m-major;            else [K][N] -> k-major.
// All inputs must already be tf32-rounded in gmem (raw cp.async copies).
template<bool TA, bool TB>
__global__ __launch_bounds__(256, 2) void gemm_cp(
    const float* __restrict__ A, long strideA, int lda,
    const float* __restrict__ B, long strideB, int ldb,
    float* __restrict__ C, long strideC, int ldc,
    int K, const float* __restrict__ bias, const float* __restrict__ resid,
    float scale, int roundOut)
{
    extern __shared__ char smem[];
    const uint32_t sbase = smem_u32(smem);

    const int bz = blockIdx.z;
    const int m0 = blockIdx.y * 128, n0 = blockIdx.x * 128;
    const float* Ab = A + (size_t)bz * strideA;
    const float* Bb = B + (size_t)bz * strideB;

    const int tid  = threadIdx.x;
    const int lane = tid & 31, warp = tid >> 5;
    const int wm = warp >> 1, wn = warp & 1;      // 4 x 2 warp grid (32 x 64 tiles)
    const int g  = lane >> 2, tg = lane & 3;

    float acc[2][8][4];
#pragma unroll
    for (int i = 0; i < 2; i++)
#pragma unroll
        for (int j = 0; j < 8; j++)
#pragma unroll
            for (int c = 0; c < 4; c++) acc[i][j][c] = 0.f;

    const int nsteps = K / 16;

    auto issue = [&](int step) {
        const int s = step & (STAGES - 1);
        const uint32_t sa  = sbase + s * STG;
        const uint32_t sbb = sbase + STAGES * STG + s * STG;
        const int k0 = step * 16;
#pragma unroll
        for (int i = 0; i < 2; i++) {
            int idx = tid + i * 256;
            if (TA) { int m = idx >> 2, kq = idx & 3;
                cpa16(sa + m * 80 + kq * 16,
                      Ab + (size_t)(m0 + m) * lda + k0 + kq * 4); }
            else    { int kk = idx >> 5, m4 = idx & 31;
                cpa16(sa + kk * 544 + m4 * 16,
                      Ab + (size_t)(k0 + kk) * lda + m0 + m4 * 4); }
        }
#pragma unroll
        for (int i = 0; i < 2; i++) {
            int idx = tid + i * 256;
            if (TB) { int n = idx >> 2, kq = idx & 3;
                cpa16(sbb + n * 80 + kq * 16,
                      Bb + (size_t)(n0 + n) * ldb + k0 + kq * 4); }
            else    { int kk = idx >> 5, n4 = idx & 31;
                cpa16(sbb + kk * 544 + n4 * 16,
                      Bb + (size_t)(k0 + kk) * ldb + n0 + n4 * 4); }
        }
        asm volatile("cp.async.commit_group;" ::: "memory");
    };

    // fragment registers: two kk-halves in flight
    uint32_t fa[2][2][4];   // [half][mi][reg]
    uint32_t fb[2][8][2];   // [half][ni][reg]

    auto ldfrags = [&](const float* SA, const float* SB, int kk, int h) {
#pragma unroll
        for (int mi = 0; mi < 2; mi++) {
            int mb = wm * 32 + mi * 16;
            if (TA) {
                fa[h][mi][0] = fbits(SA[(mb + g)     * 20 + kk + tg]);
                fa[h][mi][1] = fbits(SA[(mb + 8 + g) * 20 + kk + tg]);
                fa[h][mi][2] = fbits(SA[(mb + g)     * 20 + kk + tg + 4]);
                fa[h][mi][3] = fbits(SA[(mb + 8 + g) * 20 + kk + tg + 4]);
            } else {
                fa[h][mi][0] = fbits(SA[(kk + tg)     * 136 + mb + g]);
                fa[h][mi][1] = fbits(SA[(kk + tg)     * 136 + mb + 8 + g]);
                fa[h][mi][2] = fbits(SA[(kk + tg + 4) * 136 + mb + g]);
                fa[h][mi][3] = fbits(SA[(kk + tg + 4) * 136 + mb + 8 + g]);
            }
        }
#pragma unroll
        for (int ni = 0; ni < 8; ni++) {
            int nb2 = wn * 64 + ni * 8;
            if (TB) {
                fb[h][ni][0] = fbits(SB[(nb2 + g) * 20 + kk + tg]);
                fb[h][ni][1] = fbits(SB[(nb2 + g) * 20 + kk + tg + 4]);
            } else {
                fb[h][ni][0] = fbits(SB[(kk + tg)     * 136 + nb2 + g]);
                fb[h][ni][1] = fbits(SB[(kk + tg + 4) * 136 + nb2 + g]);
            }
        }
    };

    // prologue: STAGES-1 groups in flight
#pragma unroll
    for (int p = 0; p < STAGES - 1; p++) issue(p);

    for (int t = 0; t < nsteps; t++) {
        asm volatile("cp.async.wait_group %0;" :: "n"(STAGES - 2) : "memory");
        __syncthreads();
        if (t + STAGES - 1 < nsteps) issue(t + STAGES - 1);
        else asm volatile("cp.async.commit_group;" ::: "memory");

        const float* SA = (const float*)(smem + (size_t)(t & (STAGES - 1)) * STG);
        const float* SB = (const float*)(smem + (size_t)STAGES * STG
                                              + (size_t)(t & (STAGES - 1)) * STG);
        ldfrags(SA, SB, 0, 0);          // half 0 fragments
#pragma unroll
        for (int h = 0; h < 2; h++) {
            if (h == 0) ldfrags(SA, SB, 8, 1);   // prefetch half 1 under half-0 MMAs
#pragma unroll
            for (int ni = 0; ni < 8; ni++) {
                mma8(acc[0][ni], fa[h][0][0], fa[h][0][1], fa[h][0][2], fa[h][0][3],
                     fb[h][ni][0], fb[h][ni][1]);
                mma8(acc[1][ni], fa[h][1][0], fa[h][1][1], fa[h][1][2], fa[h][1][3],
                     fb[h][ni][0], fb[h][ni][1]);
            }
        }
    }

    // ---- epilogue ----
    float*       Cb = C + (size_t)bz * strideC;
    const float* Rb = resid ? resid + (size_t)bz * strideC : nullptr;
#pragma unroll
    for (int mi = 0; mi < 2; mi++) {
#pragma unroll
        for (int half = 0; half < 2; half++) {
            int m = m0 + wm * 32 + mi * 16 + g + half * 8;
            float bv = bias ? bias[m] : 0.f;
#pragma unroll
            for (int ni = 0; ni < 8; ni++) {
                int n = n0 + wn * 64 + ni * 8 + tg * 2;
                float2 val;
                val.x = acc[mi][ni][half * 2 + 0] * scale + bv;
                val.y = acc[mi][ni][half * 2 + 1] * scale + bv;
                if (Rb) {
                    val.x += Rb[(size_t)m * ldc + n];
                    val.y += Rb[(size_t)m * ldc + n + 1];
                }
                if (roundOut) { val.x = tf32r(val.x); val.y = tf32r(val.y); }
                *(float2*)&Cb[(size_t)m * ldc + n] = val;
            }
        }
    }
}

// ---------------- row softmax, tf32-rounded output --------------------------------
__global__ __launch_bounds__(256) void softmax_rows(float* __restrict__ S)
{
    float* p = S + (size_t)blockIdx.x * NTOK;
    int tid = threadIdx.x;
    float4 v = ((float4*)p)[tid];

    __shared__ float red[256];
    float m = fmaxf(fmaxf(v.x, v.y), fmaxf(v.z, v.w));
    red[tid] = m;
    __syncthreads();
    for (int o = 128; o > 0; o >>= 1) {
        if (tid < o) red[tid] = fmaxf(red[tid], red[tid + o]);
        __syncthreads();
    }
    m = red[0];
    __syncthreads();

    v.x = __expf(v.x - m); v.y = __expf(v.y - m);
    v.z = __expf(v.z - m); v.w = __expf(v.w - m);
    red[tid] = v.x + v.y + v.z + v.w;
    __syncthreads();
    for (int o = 128; o > 0; o >>= 1) {
        if (tid < o) red[tid] += red[tid + o];
        __syncthreads();
    }
    float inv = 1.0f / red[0];
    v.x = tf32r(v.x * inv); v.y = tf32r(v.y * inv);
    v.z = tf32r(v.z * inv); v.w = tf32r(v.w * inv);
    ((float4*)p)[tid] = v;
}

// ---------------- launch ----------------------------------------------------------
extern "C" void kernel_launch(void* const* d_in, const int* in_sizes, int n_in,
                              void* d_out, int out_size)
{
    const float* x     = (const float*)d_in[0];
    const float* gamma = (const float*)d_in[1];
    const float* beta  = (const float*)d_in[2];
    const float* wq    = (const float*)d_in[3];
    const float* bq    = (const float*)d_in[4];
    const float* wk    = (const float*)d_in[5];
    const float* bk    = (const float*)d_in[6];
    const float* wv    = (const float*)d_in[7];
    const float* bv    = (const float*)d_in[8];
    const float* wp    = (const float*)d_in[9];
    const float* bp    = (const float*)d_in[10];
    float* out = (float*)d_out;

    float *hn, *qkv, *s, *o, *w, *bqkv;
    cudaGetSymbolAddress((void**)&hn,   g_hn);
    cudaGetSymbolAddress((void**)&qkv,  g_qkv);
    cudaGetSymbolAddress((void**)&s,    g_s);
    cudaGetSymbolAddress((void**)&o,    g_o);
    cudaGetSymbolAddress((void**)&w,    g_w);
    cudaGetSymbolAddress((void**)&bqkv, g_bqkv);

    cudaFuncSetAttribute(gemm_cp<true,  false>, cudaFuncAttributeMaxDynamicSharedMemorySize, SMEM_TOTAL);
    cudaFuncSetAttribute(gemm_cp<false, false>, cudaFuncAttributeMaxDynamicSharedMemorySize, SMEM_TOTAL);
    cudaFuncSetAttribute(gemm_cp<true,  true >, cudaFuncAttributeMaxDynamicSharedMemorySize, SMEM_TOTAL);

    const long sBN  = (long)CH * NTOK;     // per-batch stride of (c, n) tensors
    const long sQKV = 3 * sBN;             // per-batch stride of fused qkv
    const long sS   = (long)NTOK * NTOK;

    // 0. setup: round weights, stack qkv bias
    round_weights<<<4 * CH * CH / 1024, 256>>>(wq, wk, wv, wp, w);
    stack_bias<<<1, 512>>>(bq, bk, bv, bqkv);

    // 1. GroupNorm -> hn (channel-major, tf32)
    groupnorm_kernel<<<BATCH * NGRP, 256>>>(x, gamma, beta, hn);

    // 2. fused QKV: C(1536 x 1024) = Wqkv(row-major, TA) x hn(k-major)
    gemm_cp<true,  false><<<dim3(NTOK / 128, 3 * CH / 128, BATCH), 256, SMEM_TOTAL>>>(
        w, 0, CH,  hn, sBN, NTOK,  qkv, sQKV, NTOK,
        CH, bqkv, nullptr, 1.0f, 1);

    // 3. scores S(n,m) = q^T k * C^-0.5 (both k(=c)-major)
    gemm_cp<false, false><<<dim3(NTOK / 128, NTOK / 128, BATCH), 256, SMEM_TOTAL>>>(
        qkv, sQKV, NTOK,  qkv + sBN, sQKV, NTOK,  s, sS, NTOK,
        CH, nullptr, nullptr, 0.04419417382415922f, 0);

    // 4. softmax (in place, tf32 out)
    softmax_rows<<<BATCH * NTOK, 256>>>(s);

    // 5. O(c,n) = V(c,m; TA) x attn^T(n,m; TB), K = 1024
    dim3 g_nn(NTOK / 128, CH / 128, BATCH);
    gemm_cp<true,  true ><<<g_nn, 256, SMEM_TOTAL>>>(
        qkv + 2 * sBN, sQKV, NTOK,  s, sS, NTOK,  o, sBN, NTOK,
        NTOK, nullptr, nullptr, 1.0f, 1);

    // 6. out = Wp x o + bp + x
    gemm_cp<true,  false><<<g_nn, 256, SMEM_TOTAL>>>(
        w + 3 * CH * CH, 0, CH,  o, sBN, NTOK,  out, sBN, NTOK,
        CH, bp, x, 1.0f, 0);
}

// round 12
// speedup vs baseline: 3.8752x; 1.0824x over previous
#include <cuda_runtime.h>
#include <cstdint>

#define BATCH 32
#define CH    512
#define NGRP  16
#define CPG   32
#define NTOK  1024
#define GSIZE (CPG * NTOK)

#define NSTAGE 3
#define STG    18432                        // bytes/operand/stage: max(128*36, 32*136)*4
#define SMEM_TOTAL (2 * NSTAGE * STG)       // 110592 B

// ---------------- scratch (static device globals; runtime alloc forbidden) -------
__device__ float g_hn [(size_t)BATCH * CH * NTOK];      // (b, c, n) channel-major, tf32
__device__ float g_qkv[(size_t)BATCH * 3 * CH * NTOK];  // (b, {q,k,v}, c, n), tf32
__device__ float g_s  [(size_t)BATCH * NTOK * NTOK];    // exp(scores), tf32
__device__ float g_o  [(size_t)BATCH * CH * NTOK];
__device__ float g_w  [4 * CH * CH];                    // tf32-rounded wq|wk|wv|wp
__device__ float g_bqkv[3 * CH];
__device__ float g_rinv[(size_t)BATCH * NTOK];          // 1 / rowsum(exp)

// ---------------- helpers ---------------------------------------------------------
__device__ __forceinline__ float tf32r(float x) {
    uint32_t u;
    asm("cvt.rna.tf32.f32 %0, %1;" : "=r"(u) : "f"(x));
    return __uint_as_float(u);
}
__device__ __forceinline__ float4 tf32x4(float4 v) {
    v.x = tf32r(v.x); v.y = tf32r(v.y); v.z = tf32r(v.z); v.w = tf32r(v.w);
    return v;
}
__device__ __forceinline__ void cpa16(uint32_t s, const void* g) {
    asm volatile("cp.async.cg.shared.global [%0], [%1], 16;" :: "r"(s), "l"(g));
}
__device__ __forceinline__ uint32_t smem_u32(const void* p) {
    uint32_t a;
    asm("{ .reg .u64 t; cvta.to.shared.u64 t, %1; cvt.u32.u64 %0, t; }" : "=r"(a) : "l"(p));
    return a;
}
__device__ __forceinline__ void mma8(float c[4],
    uint32_t a0, uint32_t a1, uint32_t a2, uint32_t a3, uint32_t b0, uint32_t b1)
{
    asm volatile(
        "mma.sync.aligned.m16n8k8.row.col.f32.tf32.tf32.f32 "
        "{%0,%1,%2,%3}, {%4,%5,%6,%7}, {%8,%9}, {%0,%1,%2,%3};"
        : "+f"(c[0]), "+f"(c[1]), "+f"(c[2]), "+f"(c[3])
        : "r"(a0), "r"(a1), "r"(a2), "r"(a3), "r"(b0), "r"(b1));
}
__device__ __forceinline__ uint32_t fbits(float x) { return __float_as_uint(x); }

// ---------------- setup kernels ----------------------------------------------------
__global__ __launch_bounds__(256) void round_weights(
    const float* __restrict__ wq, const float* __restrict__ wk,
    const float* __restrict__ wv, const float* __restrict__ wp,
    float* __restrict__ w)
{
    int i = blockIdx.x * 256 + threadIdx.x;   // 4 * 65536 float4s
    int m = i >> 16, j = i & 65535;
    const float* src = (m == 0) ? wq : (m == 1) ? wk : (m == 2) ? wv : wp;
    ((float4*)(w + (size_t)m * CH * CH))[j] = tf32x4(((const float4*)src)[j]);
}
__global__ __launch_bounds__(512) void stack_bias(
    const float* __restrict__ bq, const float* __restrict__ bk,
    const float* __restrict__ bv, float* __restrict__ dst)
{
    int i = threadIdx.x;
    dst[i] = bq[i]; dst[CH + i] = bk[i]; dst[2 * CH + i] = bv[i];
}

// ---------------- GroupNorm (channel-major out, tf32-rounded) ---------------------
__global__ __launch_bounds__(256) void groupnorm_kernel(
    const float* __restrict__ x, const float* __restrict__ gamma,
    const float* __restrict__ beta, float* __restrict__ hn)
{
    int b = blockIdx.x / NGRP;
    int g = blockIdx.x % NGRP;
    const float* xp = x  + ((size_t)b * CH + g * CPG) * NTOK;
    float*       hp = hn + ((size_t)b * CH + g * CPG) * NTOK;
    int tid = threadIdx.x;

    float s = 0.f, s2 = 0.f;
    for (int i = tid; i < GSIZE; i += 256) {
        float v = xp[i];
        s += v; s2 += v * v;
    }
    __shared__ float rs[256], rs2[256];
    rs[tid] = s; rs2[tid] = s2;
    __syncthreads();
    for (int o = 128; o > 0; o >>= 1) {
        if (tid < o) { rs[tid] += rs[tid + o]; rs2[tid] += rs2[tid + o]; }
        __syncthreads();
    }
    float mean = rs[0] * (1.0f / GSIZE);
    float var  = rs2[0] * (1.0f / GSIZE) - mean * mean;
    float rstd = rsqrtf(var + 1e-6f);

    for (int i = tid * 4; i < GSIZE; i += 1024) {
        int c = g * CPG + i / NTOK;
        float gm = gamma[c], bt = beta[c];
        float4 v = *(const float4*)&xp[i];
        v.x = tf32r((v.x - mean) * rstd * gm + bt);
        v.y = tf32r((v.y - mean) * rstd * gm + bt);
        v.z = tf32r((v.z - mean) * rstd * gm + bt);
        v.w = tf32r((v.w - mean) * rstd * gm + bt);
        *(float4*)&hp[i] = v;
    }
}

// ---------------- row sum of exp-scores -> reciprocal -----------------------------
__global__ __launch_bounds__(256) void rowsum_recip(const float* __restrict__ e,
                                                    float* __restrict__ rinv)
{
    int row  = blockIdx.x * 8 + (threadIdx.x >> 5);   // one warp per row
    int lane = threadIdx.x & 31;
    const float4* p = (const float4*)(e + (size_t)row * NTOK);
    float s = 0.f;
#pragma unroll
    for (int j = 0; j < 8; j++) {
        float4 v = p[lane + 32 * j];
        s += (v.x + v.y) + (v.z + v.w);
    }
#pragma unroll
    for (int o = 16; o > 0; o >>= 1) s += __shfl_xor_sync(0xFFFFFFFFu, s, o);
    if (lane == 0) rinv[row] = 1.0f / s;
}

// ---------------- tf32 mma.sync batched GEMM, K-step 32, 3-stage cp.async ----------
// C[bz](M x N) = op(A * B). Block tile 128x128.
// TA: A row-major [M][K] -> SMEM m-major [128][36]; else [K][M] -> k-major [32][136].
// TB: same for B over N.
// expOut: C = exp(acc*scale)            (bias/resid ignored)
// colscale: C *= colscale[bz*NTOK + n]  (column scaling, for attn normalization)
// All inputs must already be tf32-rounded in gmem (raw cp.async copies).
template<bool TA, bool TB>
__global__ __launch_bounds__(256, 2) void gemm_cp(
    const float* __restrict__ A, long strideA, int lda,
    const float* __restrict__ B, long strideB, int ldb,
    float* __restrict__ C, long strideC, int ldc,
    int K, const float* __restrict__ bias, const float* __restrict__ resid,
    const float* __restrict__ colscale, float scale, int roundOut, int expOut)
{
    extern __shared__ char smem[];
    const uint32_t sbase = smem_u32(smem);

    const int bz = blockIdx.z;
    const int m0 = blockIdx.y * 128, n0 = blockIdx.x * 128;
    const float* Ab = A + (size_t)bz * strideA;
    const float* Bb = B + (size_t)bz * strideB;

    const int tid  = threadIdx.x;
    const int lane = tid & 31, warp = tid >> 5;
    const int wm = warp >> 1, wn = warp & 1;      // 4 x 2 warp grid (32 x 64 tiles)
    const int g  = lane >> 2, tg = lane & 3;

    float acc[2][8][4];
#pragma unroll
    for (int i = 0; i < 2; i++)
#pragma unroll
        for (int j = 0; j < 8; j++)
#pragma unroll
            for (int c = 0; c < 4; c++) acc[i][j][c] = 0.f;

    const int nsteps = K / 32;

    auto issue = [&](int step, int s) {
        const uint32_t sa  = sbase + s * STG;
        const uint32_t sbb = sbase + NSTAGE * STG + s * STG;
        const int k0 = step * 32;
#pragma unroll
        for (int i = 0; i < 4; i++) {
            int idx = tid + i * 256;
            if (TA) { int m = idx >> 3, kq = idx & 7;
                cpa16(sa + m * 144 + kq * 16,
                      Ab + (size_t)(m0 + m) * lda + k0 + kq * 4); }
            else    { int kk = idx >> 5, m4 = idx & 31;
                cpa16(sa + kk * 544 + m4 * 16,
                      Ab + (size_t)(k0 + kk) * lda + m0 + m4 * 4); }
        }
#pragma unroll
        for (int i = 0; i < 4; i++) {
            int idx = tid + i * 256;
            if (TB) { int n = idx >> 3, kq = idx & 7;
                cpa16(sbb + n * 144 + kq * 16,
                      Bb + (size_t)(n0 + n) * ldb + k0 + kq * 4); }
            else    { int kk = idx >> 5, n4 = idx & 31;
                cpa16(sbb + kk * 544 + n4 * 16,
                      Bb + (size_t)(k0 + kk) * ldb + n0 + n4 * 4); }
        }
        asm volatile("cp.async.commit_group;" ::: "memory");
    };

    // fragment registers: two kk-halves in flight
    uint32_t fa[2][2][4];
    uint32_t fb[2][8][2];

    auto ldfrags = [&](const float* SA, const float* SB, int kk, int h) {
#pragma unroll
        for (int mi = 0; mi < 2; mi++) {
            int mb = wm * 32 + mi * 16;
            if (TA) {
                fa[h][mi][0] = fbits(SA[(mb + g)     * 36 + kk + tg]);
                fa[h][mi][1] = fbits(SA[(mb + 8 + g) * 36 + kk + tg]);
                fa[h][mi][2] = fbits(SA[(mb + g)     * 36 + kk + tg + 4]);
                fa[h][mi][3] = fbits(SA[(mb + 8 + g) * 36 + kk + tg + 4]);
            } else {
                fa[h][mi][0] = fbits(SA[(kk + tg)     * 136 + mb + g]);
                fa[h][mi][1] = fbits(SA[(kk + tg)     * 136 + mb + 8 + g]);
                fa[h][mi][2] = fbits(SA[(kk + tg + 4) * 136 + mb + g]);
                fa[h][mi][3] = fbits(SA[(kk + tg + 4) * 136 + mb + 8 + g]);
            }
        }
#pragma unroll
        for (int ni = 0; ni < 8; ni++) {
            int nb2 = wn * 64 + ni * 8;
            if (TB) {
                fb[h][ni][0] = fbits(SB[(nb2 + g) * 36 + kk + tg]);
                fb[h][ni][1] = fbits(SB[(nb2 + g) * 36 + kk + tg + 4]);
            } else {
                fb[h][ni][0] = fbits(SB[(kk + tg)     * 136 + nb2 + g]);
                fb[h][ni][1] = fbits(SB[(kk + tg + 4) * 136 + nb2 + g]);
            }
        }
    };

    issue(0, 0);
    issue(1, 1);

    int stage = 0;
    for (int t = 0; t < nsteps; t++) {
        asm volatile("cp.async.wait_group %0;" :: "n"(NSTAGE - 2) : "memory");
        __syncthreads();
        {
            int tn = t + 2;
            if (tn < nsteps) {
                int sn = stage + 2; if (sn >= NSTAGE) sn -= NSTAGE;
                issue(tn, sn);
            } else {
                asm volatile("cp.async.commit_group;" ::: "memory");
            }
        }

        const float* SA = (const float*)(smem + (size_t)stage * STG);
        const float* SB = (const float*)(smem + (size_t)NSTAGE * STG + (size_t)stage * STG);
        ldfrags(SA, SB, 0, 0);
#pragma unroll
        for (int h = 0; h < 4; h++) {
            if (h < 3) ldfrags(SA, SB, (h + 1) * 8, (h + 1) & 1);  // prefetch next half
            const int cb = h & 1;
#pragma unroll
            for (int ni = 0; ni < 8; ni++) {
                mma8(acc[0][ni], fa[cb][0][0], fa[cb][0][1], fa[cb][0][2], fa[cb][0][3],
                     fb[cb][ni][0], fb[cb][ni][1]);
                mma8(acc[1][ni], fa[cb][1][0], fa[cb][1][1], fa[cb][1][2], fa[cb][1][3],
                     fb[cb][ni][0], fb[cb][ni][1]);
            }
        }
        if (++stage == NSTAGE) stage = 0;
    }

    // ---- epilogue ----
    float*       Cb = C + (size_t)bz * strideC;
    const float* Rb = resid    ? resid    + (size_t)bz * strideC : nullptr;
    const float* Cs = colscale ? colscale + (size_t)bz * NTOK    : nullptr;
#pragma unroll
    for (int mi = 0; mi < 2; mi++) {
#pragma unroll
        for (int half = 0; half < 2; half++) {
            int m = m0 + wm * 32 + mi * 16 + g + half * 8;
            float bv = bias ? bias[m] : 0.f;
#pragma unroll
            for (int ni = 0; ni < 8; ni++) {
                int n = n0 + wn * 64 + ni * 8 + tg * 2;
                float2 val;
                val.x = acc[mi][ni][half * 2 + 0] * scale + bv;
                val.y = acc[mi][ni][half * 2 + 1] * scale + bv;
                if (expOut) { val.x = __expf(val.x); val.y = __expf(val.y); }
                if (Cs) { val.x *= Cs[n]; val.y *= Cs[n + 1]; }
                if (Rb) {
                    val.x += Rb[(size_t)m * ldc + n];
                    val.y += Rb[(size_t)m * ldc + n + 1];
                }
                if (roundOut) { val.x = tf32r(val.x); val.y = tf32r(val.y); }
                *(float2*)&Cb[(size_t)m * ldc + n] = val;
            }
        }
    }
}

// ---------------- launch ----------------------------------------------------------
extern "C" void kernel_launch(void* const* d_in, const int* in_sizes, int n_in,
                              void* d_out, int out_size)
{
    const float* x     = (const float*)d_in[0];
    const float* gamma = (const float*)d_in[1];
    const float* beta  = (const float*)d_in[2];
    const float* wq    = (const float*)d_in[3];
    const float* bq    = (const float*)d_in[4];
    const float* wk    = (const float*)d_in[5];
    const float* bk    = (const float*)d_in[6];
    const float* wv    = (const float*)d_in[7];
    const float* bv    = (const float*)d_in[8];
    const float* wp    = (const float*)d_in[9];
    const float* bp    = (const float*)d_in[10];
    float* out = (float*)d_out;

    float *hn, *qkv, *s, *o, *w, *bqkv, *rinv;
    cudaGetSymbolAddress((void**)&hn,   g_hn);
    cudaGetSymbolAddress((void**)&qkv,  g_qkv);
    cudaGetSymbolAddress((void**)&s,    g_s);
    cudaGetSymbolAddress((void**)&o,    g_o);
    cudaGetSymbolAddress((void**)&w,    g_w);
    cudaGetSymbolAddress((void**)&bqkv, g_bqkv);
    cudaGetSymbolAddress((void**)&rinv, g_rinv);

    cudaFuncSetAttribute(gemm_cp<true,  false>, cudaFuncAttributeMaxDynamicSharedMemorySize, SMEM_TOTAL);
    cudaFuncSetAttribute(gemm_cp<false, false>, cudaFuncAttributeMaxDynamicSharedMemorySize, SMEM_TOTAL);
    cudaFuncSetAttribute(gemm_cp<true,  true >, cudaFuncAttributeMaxDynamicSharedMemorySize, SMEM_TOTAL);

    const long sBN  = (long)CH * NTOK;     // per-batch stride of (c, n) tensors
    const long sQKV = 3 * sBN;
    const long sS   = (long)NTOK * NTOK;

    // 0. setup
    round_weights<<<4 * CH * CH / 1024, 256>>>(wq, wk, wv, wp, w);
    stack_bias<<<1, 512>>>(bq, bk, bv, bqkv);

    // 1. GroupNorm -> hn (channel-major, tf32)
    groupnorm_kernel<<<BATCH * NGRP, 256>>>(x, gamma, beta, hn);

    // 2. fused QKV: C(1536 x 1024) = Wqkv(row-major, TA) x hn(k-major)
    gemm_cp<true,  false><<<dim3(NTOK / 128, 3 * CH / 128, BATCH), 256, SMEM_TOTAL>>>(
        w, 0, CH,  hn, sBN, NTOK,  qkv, sQKV, NTOK,
        CH, bqkv, nullptr, nullptr, 1.0f, 1, 0);

    // 3. e(n,m) = exp(q^T k * C^-0.5)   (softmax shift-invariant; logits O(10) -> no overflow)
    gemm_cp<false, false><<<dim3(NTOK / 128, NTOK / 128, BATCH), 256, SMEM_TOTAL>>>(
        qkv, sQKV, NTOK,  qkv + sBN, sQKV, NTOK,  s, sS, NTOK,
        CH, nullptr, nullptr, nullptr, 0.04419417382415922f, 1, 1);

    // 4. rinv[b][n] = 1 / sum_m e(n,m)
    rowsum_recip<<<BATCH * NTOK / 8, 256>>>(s, rinv);

    // 5. O(c,n) = V(c,m; TA) x e^T(n,m; TB) * rinv[n], K = 1024
    dim3 g_nn(NTOK / 128, CH / 128, BATCH);
    gemm_cp<true,  true ><<<g_nn, 256, SMEM_TOTAL>>>(
        qkv + 2 * sBN, sQKV, NTOK,  s, sS, NTOK,  o, sBN, NTOK,
        NTOK, nullptr, nullptr, rinv, 1.0f, 1, 0);

    // 6. out = Wp x o + bp + x
    gemm_cp<true,  false><<<g_nn, 256, SMEM_TOTAL>>>(
        w + 3 * CH * CH, 0, CH,  o, sBN, NTOK,  out, sBN, NTOK,
        CH, bp, x, nullptr, 1.0f, 0, 0);
}